// round 11
// baseline (speedup 1.0000x reference)
#include <cuda_runtime.h>
#include <cuda_fp16.h>
#include <math.h>
#include <stdint.h>

#define B_   2
#define L_   2048
#define DM   1024
#define DI   2048
#define DS   16
#define DTR  64
#define BL   (B_*L_)   /* 4096 rows */

#define STG  3      /* cp.async pipeline stages (gemm) */
#define CK   64     /* K halves per chunk (gemm) = 128B row */
#define TT   64     /* timesteps per scan tile */
#define CT   64     /* timesteps per conv tile */

// ---------------- scratch ----------------------------------------------------
__device__ float  g_xdbl [(size_t)BL*96];
__device__ float  g_delta[(size_t)BL*DI];

__device__ __half g_xn_h [(size_t)BL*DM];
__device__ __half g_xz_h [(size_t)BL*2*DI];
__device__ __half g_u_h  [(size_t)BL*DI];
__device__ __half g_y_h  [(size_t)BL*DI];
__device__ __half g_dt_h [(size_t)BL*DTR];
__device__ __half h_inw  [(size_t)2*DI*DM];
__device__ __half h_xpw  [(size_t)96*DI];
__device__ __half h_dtw  [(size_t)DI*DTR];
__device__ __half h_opw  [(size_t)DM*DI];

__device__ __forceinline__ float sanit(float v) {
    if (isnan(v)) return 0.f;
    if (isinf(v)) return v > 0.f ? 1e4f : -1e4f;
    return v;
}

__device__ __forceinline__ uint32_t smem_u32(const void* p) {
    uint32_t a;
    asm("{ .reg .u64 t; cvta.to.shared.u64 t, %1; cvt.u32.u64 %0, t; }"
        : "=r"(a) : "l"(p));
    return a;
}

__device__ __forceinline__ void cpa16(uint32_t dst, const void* src) {
    asm volatile("cp.async.cg.shared.global [%0], [%1], 16;\n"
                 :: "r"(dst), "l"(src) : "memory");
}

__device__ __forceinline__ void ldm_x4(unsigned* r, uint32_t addr) {
    asm volatile("ldmatrix.sync.aligned.m8n8.x4.shared.b16 {%0,%1,%2,%3}, [%4];"
                 : "=r"(r[0]), "=r"(r[1]), "=r"(r[2]), "=r"(r[3]) : "r"(addr));
}

__device__ __forceinline__ void mma_f16(float* d, const unsigned* a,
                                        unsigned b0, unsigned b1) {
    asm volatile(
        "mma.sync.aligned.m16n8k16.row.col.f32.f16.f16.f32 "
        "{%0,%1,%2,%3}, {%4,%5,%6,%7}, {%8,%9}, {%0,%1,%2,%3};"
        : "+f"(d[0]), "+f"(d[1]), "+f"(d[2]), "+f"(d[3])
        : "r"(a[0]), "r"(a[1]), "r"(a[2]), "r"(a[3]), "r"(b0), "r"(b1));
}

// fast softplus: max(v,0) + log(1 + exp(-|v|)); |abs err| ~5e-7
__device__ __forceinline__ float softplus_f(float v) {
    float p = __expf(-fabsf(v));
    return fmaxf(v, 0.f) + __logf(1.f + p);
}

// ---------------- weights fp32 -> fp16 (split for profiling order) -----------
#define NQ0 (2*DI*DM/4)
#define NQ1 (96*DI/4)
#define NQ2 (DI*DTR/4)
#define NQ3 (DM*DI/4)
__global__ void wconvA_kernel(const float* __restrict__ w0) {
    int j = blockIdx.x * blockDim.x + threadIdx.x;
    if (j >= NQ0) return;
    float4 v = ((const float4*)w0)[j];
    ((__half2*)h_inw)[2 * j]     = __floats2half2_rn(v.x, v.y);
    ((__half2*)h_inw)[2 * j + 1] = __floats2half2_rn(v.z, v.w);
}
__global__ void wconvB_kernel(const float* __restrict__ w1,
                              const float* __restrict__ w2,
                              const float* __restrict__ w3) {
    int i = blockIdx.x * blockDim.x + threadIdx.x;
    const float* s; __half* d; int j = i;
    if (j < NQ1) { s = w1; d = h_xpw; }
    else { j -= NQ1;
        if (j < NQ2) { s = w2; d = h_dtw; }
        else { j -= NQ2; if (j >= NQ3) return; s = w3; d = h_opw; }
    }
    float4 v = ((const float4*)s)[j];
    ((__half2*)d)[2 * j]     = __floats2half2_rn(v.x, v.y);
    ((__half2*)d)[2 * j + 1] = __floats2half2_rn(v.z, v.w);
}

// x_proj dt rows (96-stride fp32) -> packed 64-wide half
__global__ void dt2h_kernel() {
    int i = blockIdx.x * blockDim.x + threadIdx.x;   // quad over BL*64
    if (i >= BL * 16) return;
    int r = i >> 4, c = (i & 15) * 4;
    float4 v = *(const float4*)&g_xdbl[(size_t)r * 96 + c];
    *(__half2*)&g_dt_h[(size_t)r * 64 + c]     = __floats2half2_rn(v.x, v.y);
    *(__half2*)&g_dt_h[(size_t)r * 64 + c + 2] = __floats2half2_rn(v.z, v.w);
}

// ---------------- LayerNorm --------------------------------------------------
__global__ void ln_kernel(const float* __restrict__ x,
                          const float* __restrict__ g,
                          const float* __restrict__ b) {
    int row = blockIdx.x;
    int tid = threadIdx.x;
    const float* xr = x + (size_t)row * DM;
    float v[4];
    float s = 0.f, s2 = 0.f;
#pragma unroll
    for (int i = 0; i < 4; i++) {
        float t = sanit(xr[tid + i * 256]);
        v[i] = t; s += t; s2 += t * t;
    }
#pragma unroll
    for (int o = 16; o; o >>= 1) {
        s  += __shfl_xor_sync(0xffffffffu, s,  o);
        s2 += __shfl_xor_sync(0xffffffffu, s2, o);
    }
    __shared__ float ss[8], ss2[8], smu, srs;
    int w = tid >> 5, ln = tid & 31;
    if (ln == 0) { ss[w] = s; ss2[w] = s2; }
    __syncthreads();
    if (tid == 0) {
        float a = 0.f, a2 = 0.f;
#pragma unroll
        for (int i = 0; i < 8; i++) { a += ss[i]; a2 += ss2[i]; }
        float mu = a / DM;
        float var = fmaxf(a2 / DM - mu * mu, 0.f);
        smu = mu;
        srs = rsqrtf(var + 1e-5f);
    }
    __syncthreads();
    float mu = smu, rs = srs;
#pragma unroll
    for (int i = 0; i < 4; i++) {
        int c = tid + i * 256;
        g_xn_h[(size_t)row * DM + c] =
            __float2half_rn((v[i] - mu) * rs * g[c] + b[c]);
    }
}

// ---------------- fp16 HMMA GEMM v2: C[M,N] = A[M,K] * B[N,K]^T --------------
// Block 128x128, 4 warps (2x2), warp tile 64x64, K chunk = 64 halves.
// Register double-buffered fragments (ks+1 LDSM overlaps ks HMMA).
// epi: 0 f32 store, 1 bias+softplus f32, 2 sanitize+residual f32,
//      3 atomicAdd f32 (split-K), 4 plain fp16 store.
__global__ void __launch_bounds__(128, 2)
gemm_hf(const __half* __restrict__ A, int lda,
        const __half* __restrict__ Bw, int ldb,
        void* __restrict__ Cv, int N, int K, int epi,
        const float* __restrict__ bias, const float* __restrict__ res) {
    extern __shared__ __half sm[];
    const int tid  = threadIdx.x;
    const int lane = tid & 31;
    const int w    = tid >> 5;
    const int wm   = (w >> 1) * 64;
    const int wn   = (w & 1) * 64;
    const int bm   = blockIdx.y * 128;
    const int bn   = blockIdx.x * 128;
    const int NC   = K / CK;

    A  += (size_t)blockIdx.z * K;
    Bw += (size_t)blockIdx.z * K;

    const uint32_t smb = smem_u32(sm);

    float acc[4][8][4];
#pragma unroll
    for (int i = 0; i < 4; i++)
#pragma unroll
        for (int j = 0; j < 8; j++)
#pragma unroll
            for (int r = 0; r < 4; r++) acc[i][j][r] = 0.f;

    const int frow = tid >> 3, fseg = tid & 7;     // 16 rows x 8 segs per iter
    auto fill = [&](int c) {
        if (c < NC) {
            const int slot = c % STG;
            const int k0   = c * CK;
            const uint32_t abase = smb + (uint32_t)slot * 32768u;
            const uint32_t bbase = abase + 16384u;
#pragma unroll
            for (int i = 0; i < 8; i++) {
                int row = frow + i * 16;
                uint32_t dw = (uint32_t)row * 128u +
                              (((uint32_t)fseg * 16u) ^ (((uint32_t)row & 7u) << 4));
                cpa16(abase + dw, A + (size_t)(bm + row) * lda + k0 + fseg * 8);
                int br = bn + row; if (br > N - 1) br = N - 1;
                cpa16(bbase + dw, Bw + (size_t)br * ldb + k0 + fseg * 8);
            }
        }
        asm volatile("cp.async.commit_group;" ::: "memory");
    };

    fill(0);
    fill(1);

    const int rowin = lane & 7;
    const int gb0   = (lane >> 3) & 1;
    const int gb1   = lane >> 4;
    uint32_t abaseA[4], xrA[4];
#pragma unroll
    for (int im = 0; im < 4; im++) {
        int rowA = wm + im * 16 + gb0 * 8 + rowin;
        abaseA[im] = (uint32_t)rowA * 128u;
        xrA[im]    = ((uint32_t)rowA & 7u) << 4;
    }
    uint32_t abaseB[4], xrB[4];
#pragma unroll
    for (int jp = 0; jp < 4; jp++) {
        int rowB = wn + jp * 16 + gb1 * 8 + rowin;
        abaseB[jp] = (uint32_t)rowB * 128u;
        xrB[jp]    = ((uint32_t)rowB & 7u) << 4;
    }
    const uint32_t kA_off = (uint32_t)gb1 * 16u;
    const uint32_t kB_off = (uint32_t)gb0 * 16u;

    unsigned af[2][4][4], bf[2][4][4];

    for (int c = 0; c < NC; c++) {
        asm volatile("cp.async.wait_group 1;" ::: "memory");
        __syncthreads();
        fill(c + 2);

        const int slot = c % STG;
        const uint32_t ab = smb + (uint32_t)slot * 32768u;
        const uint32_t bb = ab + 16384u;

        // prime ks = 0 fragments
        {
            const uint32_t kbA = kA_off, kbB = kB_off;
#pragma unroll
            for (int im = 0; im < 4; im++)
                ldm_x4(af[0][im], ab + abaseA[im] + (kbA ^ xrA[im]));
#pragma unroll
            for (int jp = 0; jp < 4; jp++)
                ldm_x4(bf[0][jp], bb + abaseB[jp] + (kbB ^ xrB[jp]));
        }
#pragma unroll
        for (int ks = 0; ks < 4; ks++) {
            const int cur = ks & 1, nxt = cur ^ 1;
            if (ks < 3) {
                const uint32_t kbA = (uint32_t)(ks + 1) * 32u + kA_off;
                const uint32_t kbB = (uint32_t)(ks + 1) * 32u + kB_off;
#pragma unroll
                for (int im = 0; im < 4; im++)
                    ldm_x4(af[nxt][im], ab + abaseA[im] + (kbA ^ xrA[im]));
#pragma unroll
                for (int jp = 0; jp < 4; jp++)
                    ldm_x4(bf[nxt][jp], bb + abaseB[jp] + (kbB ^ xrB[jp]));
            }
#pragma unroll
            for (int im = 0; im < 4; im++) {
#pragma unroll
                for (int jp = 0; jp < 4; jp++) {
                    mma_f16(acc[im][2 * jp],     af[cur][im], bf[cur][jp][0], bf[cur][jp][1]);
                    mma_f16(acc[im][2 * jp + 1], af[cur][im], bf[cur][jp][2], bf[cur][jp][3]);
                }
            }
        }
    }

    float* Cf = (float*)Cv;
    __half* Ch = (__half*)Cv;
    const int t  = lane & 3;
    const int r8 = lane >> 2;
#pragma unroll
    for (int im = 0; im < 4; im++) {
#pragma unroll
        for (int jn = 0; jn < 8; jn++) {
            int m0 = bm + wm + im * 16 + r8;
            int n0 = bn + wn + jn * 8 + t * 2;
            if (n0 >= N) continue;
#pragma unroll
            for (int half = 0; half < 2; half++) {
                int m = m0 + half * 8;
                float v0 = acc[im][jn][half * 2 + 0];
                float v1 = acc[im][jn][half * 2 + 1];
                if (epi == 4) {
                    *(__half2*)&Ch[(size_t)m * N + n0] = __floats2half2_rn(v0, v1);
                    continue;
                } else if (epi == 1) {
                    v0 = softplus_f(v0 + bias[n0]);
                    v1 = softplus_f(v1 + bias[n0 + 1]);
                } else if (epi == 2) {
                    v0 = sanit(sanit(v0) + res[(size_t)m * N + n0]);
                    v1 = sanit(sanit(v1) + res[(size_t)m * N + n0 + 1]);
                } else if (epi == 3) {
                    atomicAdd(&Cf[(size_t)m * N + n0],     v0);
                    atomicAdd(&Cf[(size_t)m * N + n0 + 1], v1);
                    continue;
                }
                *(float2*)&Cf[(size_t)m * N + n0] = make_float2(v0, v1);
            }
        }
    }
}

// ---------------- causal depthwise conv (k=4) + SiLU, smem tiled -------------
__global__ void __launch_bounds__(256)
conv2_kernel(const float* __restrict__ cw, const float* __restrict__ cb) {
    __shared__ __half sx[(CT + 3) * 64];
    const int tid = threadIdx.x;
    const int r0  = blockIdx.x * CT;
    const int c0  = blockIdx.y * 64;
    const int l0  = r0 & (L_ - 1);

    for (int seg = tid; seg < (CT + 3) * 8; seg += 256) {
        int i  = seg >> 3;
        int s8 = (seg & 7) * 8;
        uint4 v = make_uint4(0, 0, 0, 0);
        if (i >= 3 || l0 > 0) {
            int g = r0 - 3 + i;
            v = *(const uint4*)&g_xz_h[(size_t)g * (2 * DI) + c0 + s8];
        }
        *(uint4*)&sx[i * 64 + s8] = v;
    }
    __syncthreads();

    const int c2 = (tid & 31) * 2;
    const int d  = c0 + c2;
    float w0[4], w1[4];
#pragma unroll
    for (int k = 0; k < 4; k++) { w0[k] = cw[d * 4 + k]; w1[k] = cw[(d + 1) * 4 + k]; }
    const float b0 = cb[d], b1 = cb[d + 1];

#pragma unroll
    for (int ii = 0; ii < 8; ii++) {
        int j = (tid >> 5) + ii * 8;
        float a0 = b0, a1 = b1;
#pragma unroll
        for (int k = 0; k < 4; k++) {
            float2 f = __half22float2(*(const __half2*)&sx[(j + k) * 64 + c2]);
            a0 = fmaf(f.x, w0[k], a0);
            a1 = fmaf(f.y, w1[k], a1);
        }
        a0 = a0 / (1.f + __expf(-a0));
        a1 = a1 / (1.f + __expf(-a1));
        *(__half2*)&g_u_h[(size_t)(r0 + j) * DI + d] = __floats2half2_rn(a0, a1);
    }
}

// ---------------- selective scan v3: 2 states/lane ---------------------------
__global__ void __launch_bounds__(256)
scan3_kernel(const float* __restrict__ A_log, const float* __restrict__ D_skip) {
    extern __shared__ char smc[];
    float*  sdp = (float*)(smc);
    __half* sup = (__half*)(smc + 16384);
    __half* szp = (__half*)(smc + 24576);
    float*  sBp = (float*)(smc + 32768);
    float*  sCp = (float*)(smc + 40960);
    float*  syp = (float*)(smc + 49152);

    const int tid = threadIdx.x;
    const int s   = tid & 7;
    const int dl  = tid >> 3;
    const int d0  = blockIdx.x * 32;
    const int b   = blockIdx.y;
    const int d   = d0 + dl;

    const float An0 = -__expf(A_log[d * DS + 2 * s]);
    const float An1 = -__expf(A_log[d * DS + 2 * s + 1]);
    const float dAn = An1 - An0;
    const float Dv  = D_skip[d];
    float h0 = 0.f, h1 = 0.f;
    const size_t rb = (size_t)b * L_;

    const uint32_t a_sd = smem_u32(sdp);
    const uint32_t a_su = smem_u32(sup);
    const uint32_t a_sz = smem_u32(szp);
    const uint32_t a_sB = smem_u32(sBp);
    const uint32_t a_sC = smem_u32(sCp);

    auto prefetch = [&](int tile, int buf) {
        size_t r0 = rb + (size_t)tile * TT;
#pragma unroll
        for (int rep = 0; rep < 2; rep++) {
            int seg = tid + rep * 256;
            int row = seg >> 3, c4 = (seg & 7) * 4;
            cpa16(a_sd + (uint32_t)(buf * 2048 + row * 32 + c4) * 4,
                  g_delta + (r0 + row) * DI + d0 + c4);
        }
        {
            int row = tid >> 2, ch = (tid & 3) * 8;
            cpa16(a_su + (uint32_t)(buf * 2048 + row * 32 + ch) * 2,
                  g_u_h + (r0 + row) * DI + d0 + ch);
        }
        {
            int row = tid >> 2, ch = (tid & 3) * 8;
            cpa16(a_sz + (uint32_t)(buf * 2048 + row * 32 + ch) * 2,
                  g_xz_h + (r0 + row) * (2 * DI) + DI + d0 + ch);
        }
        {
            int row = tid >> 2, cf = (tid & 3) * 4;
            cpa16(a_sB + (uint32_t)(buf * 1024 + row * 16 + cf) * 4,
                  g_xdbl + (r0 + row) * 96 + 64 + cf);
        }
        {
            int row = tid >> 2, cf = (tid & 3) * 4;
            cpa16(a_sC + (uint32_t)(buf * 1024 + row * 16 + cf) * 4,
                  g_xdbl + (r0 + row) * 96 + 80 + cf);
        }
        asm volatile("cp.async.commit_group;" ::: "memory");
    };

    prefetch(0, 0);
    const int NT = L_ / TT;
    for (int tile = 0; tile < NT; tile++) {
        const int buf = tile & 1;
        if (tile + 1 < NT) {
            prefetch(tile + 1, buf ^ 1);
            asm volatile("cp.async.wait_group 1;" ::: "memory");
        } else {
            asm volatile("cp.async.wait_group 0;" ::: "memory");
        }
        __syncthreads();

        const float*  pd = sdp + buf * 2048;
        const __half* pu = sup + buf * 2048;
        const __half* pz = szp + buf * 2048;
        const float*  pB = sBp + buf * 1024;
        const float*  pC = sCp + buf * 1024;
#pragma unroll 4
        for (int t = 0; t < TT; t++) {
            float dt = pd[t * 32 + dl];
            float ut = __half2float(pu[t * 32 + dl]);
            float2 Bt = *(const float2*)&pB[t * 16 + 2 * s];
            float2 Ct = *(const float2*)&pC[t * 16 + 2 * s];
            float e0 = __expf(dt * An0);
            float q  = __expf(dt * dAn);
            float du = dt * ut;
            h0 = fmaf(e0,     h0, du * Bt.x);
            h1 = fmaf(e0 * q, h1, du * Bt.y);
            float p = fmaf(h1, Ct.y, h0 * Ct.x);
            p += __shfl_xor_sync(0xffffffffu, p, 1);
            p += __shfl_xor_sync(0xffffffffu, p, 2);
            p += __shfl_xor_sync(0xffffffffu, p, 4);
            if (s == 0) {
                float z  = __half2float(pz[t * 32 + dl]);
                float sg = z / (1.f + __expf(-z));
                syp[t * 32 + dl] = (p + ut * Dv) * sg;
            }
        }
        __syncthreads();

        {
            int row = tid >> 2, col = (tid & 3) * 8;
            float4 v0 = *(const float4*)&syp[row * 32 + col];
            float4 v1 = *(const float4*)&syp[row * 32 + col + 4];
            __half2 o0 = __floats2half2_rn(v0.x, v0.y);
            __half2 o1 = __floats2half2_rn(v0.z, v0.w);
            __half2 o2 = __floats2half2_rn(v1.x, v1.y);
            __half2 o3 = __floats2half2_rn(v1.z, v1.w);
            uint4 pk = make_uint4(*(unsigned*)&o0, *(unsigned*)&o1,
                                  *(unsigned*)&o2, *(unsigned*)&o3);
            *(uint4*)&g_y_h[(rb + (size_t)tile * TT + row) * DI + d0 + col] = pk;
        }
    }
}

// ---------------- launch -----------------------------------------------------
extern "C" void kernel_launch(void* const* d_in, const int* in_sizes, int n_in,
                              void* d_out, int out_size) {
    const float* x         = (const float*)d_in[0];
    const float* ln_g      = (const float*)d_in[1];
    const float* ln_b      = (const float*)d_in[2];
    const float* in_proj_w = (const float*)d_in[3];
    const float* conv_w    = (const float*)d_in[4];
    const float* conv_b    = (const float*)d_in[5];
    const float* x_proj_w  = (const float*)d_in[6];
    const float* dt_proj_w = (const float*)d_in[7];
    const float* dt_proj_b = (const float*)d_in[8];
    const float* A_log     = (const float*)d_in[9];
    const float* D_skip    = (const float*)d_in[10];
    const float* out_proj_w= (const float*)d_in[11];
    float* out = (float*)d_out;

    float *p_xdbl, *p_delta;
    __half *p_xnh, *p_xzh, *p_uh, *p_yh, *p_dth, *p_inw, *p_xpw, *p_dtw, *p_opw;
    cudaGetSymbolAddress((void**)&p_xdbl,  g_xdbl);
    cudaGetSymbolAddress((void**)&p_delta, g_delta);
    cudaGetSymbolAddress((void**)&p_xnh,   g_xn_h);
    cudaGetSymbolAddress((void**)&p_xzh,   g_xz_h);
    cudaGetSymbolAddress((void**)&p_uh,    g_u_h);
    cudaGetSymbolAddress((void**)&p_yh,    g_y_h);
    cudaGetSymbolAddress((void**)&p_dth,   g_dt_h);
    cudaGetSymbolAddress((void**)&p_inw,   h_inw);
    cudaGetSymbolAddress((void**)&p_xpw,   h_xpw);
    cudaGetSymbolAddress((void**)&p_dtw,   h_dtw);
    cudaGetSymbolAddress((void**)&p_opw,   h_opw);

    const int SMEM_GB = STG * 32768;        // 96 KB
    const int SMEM_SC = 57344;              // 56 KB
    cudaFuncSetAttribute(gemm_hf, cudaFuncAttributeMaxDynamicSharedMemorySize,
                         SMEM_GB);
    cudaFuncSetAttribute(scan3_kernel, cudaFuncAttributeMaxDynamicSharedMemorySize,
                         SMEM_SC);

    // 0. weights fp32 -> fp16 (split so in_proj lands in the profiled slot)
    wconvA_kernel<<<(NQ0 + 255) / 256, 256>>>(in_proj_w);
    wconvB_kernel<<<(NQ1 + NQ2 + NQ3 + 255) / 256, 256>>>(x_proj_w, dt_proj_w,
                                                          out_proj_w);

    // 1. layernorm -> fp16 xn
    ln_kernel<<<BL, 256>>>(x, ln_g, ln_b);

    // 2. in_proj -> fp16 xz   (4th kernel launch: captured by ncu)
    gemm_hf<<<dim3(32, 32), 128, SMEM_GB>>>(p_xnh, DM, p_inw, DM, p_xzh,
                                            2 * DI, DM, 4, nullptr, nullptr);

    // 3. depthwise causal conv + silu -> fp16 u (smem tiled)
    conv2_kernel<<<dim3(BL / CT, DI / 64), 256>>>(conv_w, conv_b);

    // 4. x_proj (split-K x8, atomic fp32)
    cudaMemsetAsync(p_xdbl, 0, (size_t)BL * 96 * sizeof(float));
    gemm_hf<<<dim3(1, 32, 8), 128, SMEM_GB>>>(p_uh, DI, p_xpw, DI, p_xdbl,
                                              96, DI / 8, 3, nullptr, nullptr);
    dt2h_kernel<<<(BL * 16) / 256, 256>>>();

    // 5. dt_proj + softplus -> fp32 delta
    gemm_hf<<<dim3(16, 32), 128, SMEM_GB>>>(p_dth, DTR, p_dtw, DTR, p_delta,
                                            DI, DTR, 1, dt_proj_b, nullptr);

    // 6. selective scan + D-skip + silu(z) gate -> fp16 y
    scan3_kernel<<<dim3(DI / 32, B_), 256, SMEM_SC>>>(A_log, D_skip);

    // 7. out_proj + residual(x) + sanitize -> out
    gemm_hf<<<dim3(8, 32), 128, SMEM_GB>>>(p_yh, DI, p_opw, DI, out,
                                           DM, DI, 2, nullptr, x);
}

// round 12
// speedup vs baseline: 1.3397x; 1.3397x over previous
#include <cuda_runtime.h>
#include <cuda_fp16.h>
#include <math.h>
#include <stdint.h>

#define B_   2
#define L_   2048
#define DM   1024
#define DI   2048
#define DS   16
#define DTR  64
#define BL   (B_*L_)   /* 4096 rows */

#define STG  3      /* cp.async pipeline stages (gemm) */
#define CK   64     /* K halves per chunk (gemm) = 128B row */
#define TT   64     /* timesteps per scan tile */
#define CT   64     /* timesteps per conv tile */

// ---------------- scratch ----------------------------------------------------
__device__ float  g_xdbl [(size_t)BL*96];
__device__ float  g_delta[(size_t)BL*DI];

__device__ __half g_xn_h [(size_t)BL*DM];
__device__ __half g_xz_h [(size_t)BL*2*DI];
__device__ __half g_u_h  [(size_t)BL*DI];
__device__ __half g_y_h  [(size_t)BL*DI];
__device__ __half g_dt_h [(size_t)BL*DTR];
__device__ __half h_inw  [(size_t)2*DI*DM];
__device__ __half h_xpw  [(size_t)96*DI];
__device__ __half h_dtw  [(size_t)DI*DTR];
__device__ __half h_opw  [(size_t)DM*DI];

__device__ __forceinline__ float sanit(float v) {
    if (isnan(v)) return 0.f;
    if (isinf(v)) return v > 0.f ? 1e4f : -1e4f;
    return v;
}

__device__ __forceinline__ uint32_t smem_u32(const void* p) {
    uint32_t a;
    asm("{ .reg .u64 t; cvta.to.shared.u64 t, %1; cvt.u32.u64 %0, t; }"
        : "=r"(a) : "l"(p));
    return a;
}

__device__ __forceinline__ void cpa16(uint32_t dst, const void* src) {
    asm volatile("cp.async.cg.shared.global [%0], [%1], 16;\n"
                 :: "r"(dst), "l"(src) : "memory");
}
__device__ __forceinline__ void cpa8(uint32_t dst, const void* src) {
    asm volatile("cp.async.ca.shared.global [%0], [%1], 8;\n"
                 :: "r"(dst), "l"(src) : "memory");
}

__device__ __forceinline__ void ldm_x4(unsigned* r, uint32_t addr) {
    asm volatile("ldmatrix.sync.aligned.m8n8.x4.shared.b16 {%0,%1,%2,%3}, [%4];"
                 : "=r"(r[0]), "=r"(r[1]), "=r"(r[2]), "=r"(r[3]) : "r"(addr));
}

__device__ __forceinline__ void mma_f16(float* d, const unsigned* a,
                                        unsigned b0, unsigned b1) {
    asm volatile(
        "mma.sync.aligned.m16n8k16.row.col.f32.f16.f16.f32 "
        "{%0,%1,%2,%3}, {%4,%5,%6,%7}, {%8,%9}, {%0,%1,%2,%3};"
        : "+f"(d[0]), "+f"(d[1]), "+f"(d[2]), "+f"(d[3])
        : "r"(a[0]), "r"(a[1]), "r"(a[2]), "r"(a[3]), "r"(b0), "r"(b1));
}

// fast softplus: max(v,0) + log(1 + exp(-|v|)); |abs err| ~5e-7
__device__ __forceinline__ float softplus_f(float v) {
    float p = __expf(-fabsf(v));
    return fmaxf(v, 0.f) + __logf(1.f + p);
}

// ---------------- weights fp32 -> fp16 ---------------------------------------
#define NQ0 (2*DI*DM/4)
#define NQ1 (96*DI/4)
#define NQ2 (DI*DTR/4)
#define NQ3 (DM*DI/4)
#define NXD (BL*96/4)
__global__ void wconvA_kernel(const float* __restrict__ w0) {
    int j = blockIdx.x * blockDim.x + threadIdx.x;
    if (j >= NQ0) return;
    float4 v = ((const float4*)w0)[j];
    ((__half2*)h_inw)[2 * j]     = __floats2half2_rn(v.x, v.y);
    ((__half2*)h_inw)[2 * j + 1] = __floats2half2_rn(v.z, v.w);
}
// converts x_proj/dt_proj/out_proj weights AND zeroes g_xdbl (replaces memset)
__global__ void wconvB_kernel(const float* __restrict__ w1,
                              const float* __restrict__ w2,
                              const float* __restrict__ w3) {
    int i = blockIdx.x * blockDim.x + threadIdx.x;
    if (i < NXD)
        ((float4*)g_xdbl)[i] = make_float4(0.f, 0.f, 0.f, 0.f);
    const float* s; __half* d; int j = i;
    if (j < NQ1) { s = w1; d = h_xpw; }
    else { j -= NQ1;
        if (j < NQ2) { s = w2; d = h_dtw; }
        else { j -= NQ2; if (j >= NQ3) return; s = w3; d = h_opw; }
    }
    float4 v = ((const float4*)s)[j];
    ((__half2*)d)[2 * j]     = __floats2half2_rn(v.x, v.y);
    ((__half2*)d)[2 * j + 1] = __floats2half2_rn(v.z, v.w);
}

// x_proj dt rows (96-stride fp32) -> packed 64-wide half
__global__ void dt2h_kernel() {
    int i = blockIdx.x * blockDim.x + threadIdx.x;   // quad over BL*64
    if (i >= BL * 16) return;
    int r = i >> 4, c = (i & 15) * 4;
    float4 v = *(const float4*)&g_xdbl[(size_t)r * 96 + c];
    *(__half2*)&g_dt_h[(size_t)r * 64 + c]     = __floats2half2_rn(v.x, v.y);
    *(__half2*)&g_dt_h[(size_t)r * 64 + c + 2] = __floats2half2_rn(v.z, v.w);
}

// ---------------- LayerNorm (float4 vectorized) ------------------------------
__global__ void ln_kernel(const float* __restrict__ x,
                          const float* __restrict__ g,
                          const float* __restrict__ b) {
    int row = blockIdx.x;
    int tid = threadIdx.x;
    float4 xv = ((const float4*)(x + (size_t)row * DM))[tid];
    float v[4] = {sanit(xv.x), sanit(xv.y), sanit(xv.z), sanit(xv.w)};
    float s = 0.f, s2 = 0.f;
#pragma unroll
    for (int i = 0; i < 4; i++) { s += v[i]; s2 += v[i] * v[i]; }
#pragma unroll
    for (int o = 16; o; o >>= 1) {
        s  += __shfl_xor_sync(0xffffffffu, s,  o);
        s2 += __shfl_xor_sync(0xffffffffu, s2, o);
    }
    __shared__ float ss[8], ss2[8], smu, srs;
    int w = tid >> 5, ln = tid & 31;
    if (ln == 0) { ss[w] = s; ss2[w] = s2; }
    __syncthreads();
    if (tid == 0) {
        float a = 0.f, a2 = 0.f;
#pragma unroll
        for (int i = 0; i < 8; i++) { a += ss[i]; a2 += ss2[i]; }
        float mu = a / DM;
        float var = fmaxf(a2 / DM - mu * mu, 0.f);
        smu = mu;
        srs = rsqrtf(var + 1e-5f);
    }
    __syncthreads();
    float mu = smu, rs = srs;
    float4 gv = ((const float4*)g)[tid];
    float4 bv = ((const float4*)b)[tid];
    float r0 = (v[0] - mu) * rs * gv.x + bv.x;
    float r1 = (v[1] - mu) * rs * gv.y + bv.y;
    float r2 = (v[2] - mu) * rs * gv.z + bv.z;
    float r3 = (v[3] - mu) * rs * gv.w + bv.w;
    __half2 o0 = __floats2half2_rn(r0, r1);
    __half2 o1 = __floats2half2_rn(r2, r3);
    uint2 pk = make_uint2(*(unsigned*)&o0, *(unsigned*)&o1);
    *(uint2*)&g_xn_h[(size_t)row * DM + tid * 4] = pk;
}

// ---------------- fp16 HMMA GEMM v2: C[M,N] = A[M,K] * B[N,K]^T --------------
// Block 128x128, 4 warps (2x2), warp tile 64x64, reg double-buffered frags.
// epi: 0 f32, 1 bias+softplus f32, 2 sanitize+residual f32, 3 atomicAdd f32,
//      4 fp16 store.
__global__ void __launch_bounds__(128, 2)
gemm_hf(const __half* __restrict__ A, int lda,
        const __half* __restrict__ Bw, int ldb,
        void* __restrict__ Cv, int N, int K, int epi,
        const float* __restrict__ bias, const float* __restrict__ res) {
    extern __shared__ __half sm[];
    const int tid  = threadIdx.x;
    const int lane = tid & 31;
    const int w    = tid >> 5;
    const int wm   = (w >> 1) * 64;
    const int wn   = (w & 1) * 64;
    const int bm   = blockIdx.y * 128;
    const int bn   = blockIdx.x * 128;
    const int NC   = K / CK;

    A  += (size_t)blockIdx.z * K;
    Bw += (size_t)blockIdx.z * K;

    const uint32_t smb = smem_u32(sm);

    float acc[4][8][4];
#pragma unroll
    for (int i = 0; i < 4; i++)
#pragma unroll
        for (int j = 0; j < 8; j++)
#pragma unroll
            for (int r = 0; r < 4; r++) acc[i][j][r] = 0.f;

    const int frow = tid >> 3, fseg = tid & 7;
    auto fill = [&](int c) {
        if (c < NC) {
            const int slot = c % STG;
            const int k0   = c * CK;
            const uint32_t abase = smb + (uint32_t)slot * 32768u;
            const uint32_t bbase = abase + 16384u;
#pragma unroll
            for (int i = 0; i < 8; i++) {
                int row = frow + i * 16;
                uint32_t dw = (uint32_t)row * 128u +
                              (((uint32_t)fseg * 16u) ^ (((uint32_t)row & 7u) << 4));
                cpa16(abase + dw, A + (size_t)(bm + row) * lda + k0 + fseg * 8);
                int br = bn + row; if (br > N - 1) br = N - 1;
                cpa16(bbase + dw, Bw + (size_t)br * ldb + k0 + fseg * 8);
            }
        }
        asm volatile("cp.async.commit_group;" ::: "memory");
    };

    fill(0);
    fill(1);

    const int rowin = lane & 7;
    const int gb0   = (lane >> 3) & 1;
    const int gb1   = lane >> 4;
    uint32_t abaseA[4], xrA[4];
#pragma unroll
    for (int im = 0; im < 4; im++) {
        int rowA = wm + im * 16 + gb0 * 8 + rowin;
        abaseA[im] = (uint32_t)rowA * 128u;
        xrA[im]    = ((uint32_t)rowA & 7u) << 4;
    }
    uint32_t abaseB[4], xrB[4];
#pragma unroll
    for (int jp = 0; jp < 4; jp++) {
        int rowB = wn + jp * 16 + gb1 * 8 + rowin;
        abaseB[jp] = (uint32_t)rowB * 128u;
        xrB[jp]    = ((uint32_t)rowB & 7u) << 4;
    }
    const uint32_t kA_off = (uint32_t)gb1 * 16u;
    const uint32_t kB_off = (uint32_t)gb0 * 16u;

    unsigned af[2][4][4], bf[2][4][4];

    for (int c = 0; c < NC; c++) {
        asm volatile("cp.async.wait_group 1;" ::: "memory");
        __syncthreads();
        fill(c + 2);

        const int slot = c % STG;
        const uint32_t ab = smb + (uint32_t)slot * 32768u;
        const uint32_t bb = ab + 16384u;

        {
            const uint32_t kbA = kA_off, kbB = kB_off;
#pragma unroll
            for (int im = 0; im < 4; im++)
                ldm_x4(af[0][im], ab + abaseA[im] + (kbA ^ xrA[im]));
#pragma unroll
            for (int jp = 0; jp < 4; jp++)
                ldm_x4(bf[0][jp], bb + abaseB[jp] + (kbB ^ xrB[jp]));
        }
#pragma unroll
        for (int ks = 0; ks < 4; ks++) {
            const int cur = ks & 1, nxt = cur ^ 1;
            if (ks < 3) {
                const uint32_t kbA = (uint32_t)(ks + 1) * 32u + kA_off;
                const uint32_t kbB = (uint32_t)(ks + 1) * 32u + kB_off;
#pragma unroll
                for (int im = 0; im < 4; im++)
                    ldm_x4(af[nxt][im], ab + abaseA[im] + (kbA ^ xrA[im]));
#pragma unroll
                for (int jp = 0; jp < 4; jp++)
                    ldm_x4(bf[nxt][jp], bb + abaseB[jp] + (kbB ^ xrB[jp]));
            }
#pragma unroll
            for (int im = 0; im < 4; im++) {
#pragma unroll
                for (int jp = 0; jp < 4; jp++) {
                    mma_f16(acc[im][2 * jp],     af[cur][im], bf[cur][jp][0], bf[cur][jp][1]);
                    mma_f16(acc[im][2 * jp + 1], af[cur][im], bf[cur][jp][2], bf[cur][jp][3]);
                }
            }
        }
    }

    float* Cf = (float*)Cv;
    __half* Ch = (__half*)Cv;
    const int t  = lane & 3;
    const int r8 = lane >> 2;
#pragma unroll
    for (int im = 0; im < 4; im++) {
#pragma unroll
        for (int jn = 0; jn < 8; jn++) {
            int m0 = bm + wm + im * 16 + r8;
            int n0 = bn + wn + jn * 8 + t * 2;
            if (n0 >= N) continue;
#pragma unroll
            for (int half = 0; half < 2; half++) {
                int m = m0 + half * 8;
                float v0 = acc[im][jn][half * 2 + 0];
                float v1 = acc[im][jn][half * 2 + 1];
                if (epi == 4) {
                    *(__half2*)&Ch[(size_t)m * N + n0] = __floats2half2_rn(v0, v1);
                    continue;
                } else if (epi == 1) {
                    v0 = softplus_f(v0 + bias[n0]);
                    v1 = softplus_f(v1 + bias[n0 + 1]);
                } else if (epi == 2) {
                    v0 = sanit(sanit(v0) + res[(size_t)m * N + n0]);
                    v1 = sanit(sanit(v1) + res[(size_t)m * N + n0 + 1]);
                } else if (epi == 3) {
                    atomicAdd(&Cf[(size_t)m * N + n0],     v0);
                    atomicAdd(&Cf[(size_t)m * N + n0 + 1], v1);
                    continue;
                }
                *(float2*)&Cf[(size_t)m * N + n0] = make_float2(v0, v1);
            }
        }
    }
}

// ---------------- causal depthwise conv (k=4) + SiLU, smem tiled -------------
__global__ void __launch_bounds__(256)
conv2_kernel(const float* __restrict__ cw, const float* __restrict__ cb) {
    __shared__ __half sx[(CT + 3) * 64];
    const int tid = threadIdx.x;
    const int r0  = blockIdx.x * CT;
    const int c0  = blockIdx.y * 64;
    const int l0  = r0 & (L_ - 1);

    for (int seg = tid; seg < (CT + 3) * 8; seg += 256) {
        int i  = seg >> 3;
        int s8 = (seg & 7) * 8;
        uint4 v = make_uint4(0, 0, 0, 0);
        if (i >= 3 || l0 > 0) {
            int g = r0 - 3 + i;
            v = *(const uint4*)&g_xz_h[(size_t)g * (2 * DI) + c0 + s8];
        }
        *(uint4*)&sx[i * 64 + s8] = v;
    }
    __syncthreads();

    const int c2 = (tid & 31) * 2;
    const int d  = c0 + c2;
    float w0[4], w1[4];
#pragma unroll
    for (int k = 0; k < 4; k++) { w0[k] = cw[d * 4 + k]; w1[k] = cw[(d + 1) * 4 + k]; }
    const float b0 = cb[d], b1 = cb[d + 1];

#pragma unroll
    for (int ii = 0; ii < 8; ii++) {
        int j = (tid >> 5) + ii * 8;
        float a0 = b0, a1 = b1;
#pragma unroll
        for (int k = 0; k < 4; k++) {
            float2 f = __half22float2(*(const __half2*)&sx[(j + k) * 64 + c2]);
            a0 = fmaf(f.x, w0[k], a0);
            a1 = fmaf(f.y, w1[k], a1);
        }
        a0 = a0 / (1.f + __expf(-a0));
        a1 = a1 / (1.f + __expf(-a1));
        *(__half2*)&g_u_h[(size_t)(r0 + j) * DI + d] = __floats2half2_rn(a0, a1);
    }
}

// ---------------- selective scan v4 -------------------------------------------
// 2 states/lane, BC zipped into one LDS.128, gate applied in write-out.
// block = 256 threads = 32 channels x 8 lanes; grid (DI/32, B_).
__global__ void __launch_bounds__(256)
scan3_kernel(const float* __restrict__ A_log, const float* __restrict__ D_skip) {
    extern __shared__ char smc[];
    float*  sdp  = (float*)(smc);              // [2][64][32] f32 (16KB)
    __half* sup  = (__half*)(smc + 16384);     // [2][64][32] f16 (8KB)
    __half* szp  = (__half*)(smc + 24576);     // [2][64][32] f16 (8KB)
    float*  sbc  = (float*)(smc + 32768);      // [2][64][32] f32 zipped BC (16KB)
    float*  syp  = (float*)(smc + 49152);      // [64][32]    f32 (8KB)

    const int tid = threadIdx.x;
    const int s   = tid & 7;
    const int dl  = tid >> 3;
    const int d0  = blockIdx.x * 32;
    const int b   = blockIdx.y;
    const int d   = d0 + dl;

    const float An0 = -__expf(A_log[d * DS + 2 * s]);
    const float An1 = -__expf(A_log[d * DS + 2 * s + 1]);
    const float dAn = An1 - An0;
    const float Dv  = D_skip[d];
    float h0 = 0.f, h1 = 0.f;
    const size_t rb = (size_t)b * L_;

    const uint32_t a_sd  = smem_u32(sdp);
    const uint32_t a_su  = smem_u32(sup);
    const uint32_t a_sz  = smem_u32(szp);
    const uint32_t a_sbc = smem_u32(sbc);

    auto prefetch = [&](int tile, int buf) {
        size_t r0 = rb + (size_t)tile * TT;
#pragma unroll
        for (int rep = 0; rep < 2; rep++) {                 // delta f32: 512 segs
            int seg = tid + rep * 256;
            int row = seg >> 3, c4 = (seg & 7) * 4;
            cpa16(a_sd + (uint32_t)(buf * 2048 + row * 32 + c4) * 4,
                  g_delta + (r0 + row) * DI + d0 + c4);
        }
        {                                                    // u f16
            int row = tid >> 2, ch = (tid & 3) * 8;
            cpa16(a_su + (uint32_t)(buf * 2048 + row * 32 + ch) * 2,
                  g_u_h + (r0 + row) * DI + d0 + ch);
        }
        {                                                    // z f16
            int row = tid >> 2, ch = (tid & 3) * 8;
            cpa16(a_sz + (uint32_t)(buf * 2048 + row * 32 + ch) * 2,
                  g_xz_h + (r0 + row) * (2 * DI) + DI + d0 + ch);
        }
        // zipped BC: dst[row][s*4 + {0,1}=B2s.., {2,3}=C2s..]; 1024 8B segs
#pragma unroll
        for (int rep = 0; rep < 4; rep++) {
            int seg  = tid + rep * 256;
            int row  = seg >> 4;
            int k    = seg & 15;
            int sg   = k >> 1;
            int half = k & 1;                                // 0 = B, 1 = C
            cpa8(a_sbc + (uint32_t)(buf * 2048 + row * 32 + sg * 4 + half * 2) * 4,
                 g_xdbl + (r0 + row) * 96 + 64 + half * 16 + 2 * sg);
        }
        asm volatile("cp.async.commit_group;" ::: "memory");
    };

    prefetch(0, 0);
    const int NT = L_ / TT;
    for (int tile = 0; tile < NT; tile++) {
        const int buf = tile & 1;
        if (tile + 1 < NT) {
            prefetch(tile + 1, buf ^ 1);
            asm volatile("cp.async.wait_group 1;" ::: "memory");
        } else {
            asm volatile("cp.async.wait_group 0;" ::: "memory");
        }
        __syncthreads();

        const float*  pd  = sdp + buf * 2048;
        const __half* pu  = sup + buf * 2048;
        const float*  pbc = sbc + buf * 2048;
#pragma unroll 4
        for (int t = 0; t < TT; t++) {
            float dt = pd[t * 32 + dl];
            float ut = __half2float(pu[t * 32 + dl]);
            float4 bc = *(const float4*)&pbc[t * 32 + s * 4];  // B0,B1,C0,C1
            float e0 = __expf(dt * An0);
            float q  = __expf(dt * dAn);
            float du = dt * ut;
            h0 = fmaf(e0,     h0, du * bc.x);
            h1 = fmaf(e0 * q, h1, du * bc.y);
            float p = fmaf(h1, bc.w, h0 * bc.z);
            p += __shfl_xor_sync(0xffffffffu, p, 1);
            p += __shfl_xor_sync(0xffffffffu, p, 2);
            p += __shfl_xor_sync(0xffffffffu, p, 4);
            if (s == 0)
                syp[t * 32 + dl] = p + ut * Dv;   // pre-gate
        }
        __syncthreads();

        // write-out: apply silu(z) gate here (out of the serial loop)
        {
            int row = tid >> 2, col = (tid & 3) * 8;
            float4 v0 = *(const float4*)&syp[row * 32 + col];
            float4 v1 = *(const float4*)&syp[row * 32 + col + 4];
            uint4 zb = *(const uint4*)&szp[buf * 2048 + row * 32 + col];
            float2 z0 = __half22float2(*(__half2*)&zb.x);
            float2 z1 = __half22float2(*(__half2*)&zb.y);
            float2 z2 = __half22float2(*(__half2*)&zb.z);
            float2 z3 = __half22float2(*(__half2*)&zb.w);
            float y[8];
            y[0] = v0.x * (z0.x / (1.f + __expf(-z0.x)));
            y[1] = v0.y * (z0.y / (1.f + __expf(-z0.y)));
            y[2] = v0.z * (z1.x / (1.f + __expf(-z1.x)));
            y[3] = v0.w * (z1.y / (1.f + __expf(-z1.y)));
            y[4] = v1.x * (z2.x / (1.f + __expf(-z2.x)));
            y[5] = v1.y * (z2.y / (1.f + __expf(-z2.y)));
            y[6] = v1.z * (z3.x / (1.f + __expf(-z3.x)));
            y[7] = v1.w * (z3.y / (1.f + __expf(-z3.y)));
            __half2 o0 = __floats2half2_rn(y[0], y[1]);
            __half2 o1 = __floats2half2_rn(y[2], y[3]);
            __half2 o2 = __floats2half2_rn(y[4], y[5]);
            __half2 o3 = __floats2half2_rn(y[6], y[7]);
            uint4 pk = make_uint4(*(unsigned*)&o0, *(unsigned*)&o1,
                                  *(unsigned*)&o2, *(unsigned*)&o3);
            *(uint4*)&g_y_h[(rb + (size_t)tile * TT + row) * DI + d0 + col] = pk;
        }
    }
}

// ---------------- launch -----------------------------------------------------
extern "C" void kernel_launch(void* const* d_in, const int* in_sizes, int n_in,
                              void* d_out, int out_size) {
    const float* x         = (const float*)d_in[0];
    const float* ln_g      = (const float*)d_in[1];
    const float* ln_b      = (const float*)d_in[2];
    const float* in_proj_w = (const float*)d_in[3];
    const float* conv_w    = (const float*)d_in[4];
    const float* conv_b    = (const float*)d_in[5];
    const float* x_proj_w  = (const float*)d_in[6];
    const float* dt_proj_w = (const float*)d_in[7];
    const float* dt_proj_b = (const float*)d_in[8];
    const float* A_log     = (const float*)d_in[9];
    const float* D_skip    = (const float*)d_in[10];
    const float* out_proj_w= (const float*)d_in[11];
    float* out = (float*)d_out;

    float *p_xdbl, *p_delta;
    __half *p_xnh, *p_xzh, *p_uh, *p_yh, *p_dth, *p_inw, *p_xpw, *p_dtw, *p_opw;
    cudaGetSymbolAddress((void**)&p_xdbl,  g_xdbl);
    cudaGetSymbolAddress((void**)&p_delta, g_delta);
    cudaGetSymbolAddress((void**)&p_xnh,   g_xn_h);
    cudaGetSymbolAddress((void**)&p_xzh,   g_xz_h);
    cudaGetSymbolAddress((void**)&p_uh,    g_u_h);
    cudaGetSymbolAddress((void**)&p_yh,    g_y_h);
    cudaGetSymbolAddress((void**)&p_dth,   g_dt_h);
    cudaGetSymbolAddress((void**)&p_inw,   h_inw);
    cudaGetSymbolAddress((void**)&p_xpw,   h_xpw);
    cudaGetSymbolAddress((void**)&p_dtw,   h_dtw);
    cudaGetSymbolAddress((void**)&p_opw,   h_opw);

    const int SMEM_GB = STG * 32768;        // 96 KB
    const int SMEM_SC = 57344;              // 56 KB
    cudaFuncSetAttribute(gemm_hf, cudaFuncAttributeMaxDynamicSharedMemorySize,
                         SMEM_GB);
    cudaFuncSetAttribute(scan3_kernel, cudaFuncAttributeMaxDynamicSharedMemorySize,
                         SMEM_SC);

    // 0. weights fp32 -> fp16 (wconvB also zeroes g_xdbl for split-K atomics)
    wconvA_kernel<<<(NQ0 + 255) / 256, 256>>>(in_proj_w);
    wconvB_kernel<<<(NQ1 + NQ2 + NQ3 + 255) / 256, 256>>>(x_proj_w, dt_proj_w,
                                                          out_proj_w);

    // 1. layernorm -> fp16 xn
    ln_kernel<<<BL, 256>>>(x, ln_g, ln_b);

    // 2. in_proj -> fp16 xz   (4th launch: profiled slot)
    gemm_hf<<<dim3(32, 32), 128, SMEM_GB>>>(p_xnh, DM, p_inw, DM, p_xzh,
                                            2 * DI, DM, 4, nullptr, nullptr);

    // 3. depthwise causal conv + silu -> fp16 u (smem tiled)
    conv2_kernel<<<dim3(BL / CT, DI / 64), 256>>>(conv_w, conv_b);

    // 4. x_proj (split-K x8, atomic fp32 into pre-zeroed xdbl)
    gemm_hf<<<dim3(1, 32, 8), 128, SMEM_GB>>>(p_uh, DI, p_xpw, DI, p_xdbl,
                                              96, DI / 8, 3, nullptr, nullptr);
    dt2h_kernel<<<(BL * 16) / 256, 256>>>();

    // 5. dt_proj + softplus -> fp32 delta
    gemm_hf<<<dim3(16, 32), 128, SMEM_GB>>>(p_dth, DTR, p_dtw, DTR, p_delta,
                                            DI, DTR, 1, dt_proj_b, nullptr);

    // 6. selective scan + D-skip + silu(z) gate -> fp16 y
    scan3_kernel<<<dim3(DI / 32, B_), 256, SMEM_SC>>>(A_log, D_skip);

    // 7. out_proj + residual(x) + sanitize -> out
    gemm_hf<<<dim3(8, 32), 128, SMEM_GB>>>(p_yh, DI, p_opw, DI, out,
                                           DM, DI, 2, nullptr, x);
}